// round 1
// baseline (speedup 1.0000x reference)
#include <cuda_runtime.h>
#include <cstdint>

#define BATCH 512
#define CHAN  1024
#define HW    64        // 8x8
#define EPS_F 1e-8f
#define TINY_F 1.17549435e-38f

// scratch: per-batch gate [512][64]
__device__ float g_gate[BATCH * HW];

// ---------------------------------------------------------------------------
// Threefry-2x32-20 (JAX), key = (0,1)  (jax.random.key(1))
// counter array = iota(32768) split into halves (c0 = i, c1 = i + 16384)
// output layout: out[i] = x0 for i < 16384 else x1 of pair (i-16384, i)
// ---------------------------------------------------------------------------
__device__ __forceinline__ unsigned rotl32(unsigned x, int r) {
    return (x << r) | (x >> (32 - r));
}

__device__ __forceinline__ unsigned threefry_out(unsigned idx) {
    const unsigned half = 16384u;
    unsigned c0, c1;
    bool first = (idx < half);
    if (first) { c0 = idx; c1 = idx + half; }
    else       { c0 = idx - half; c1 = idx; }

    const unsigned ks0 = 0u, ks1 = 1u, ks2 = 0x1BD11BDAu ^ 0u ^ 1u; // 0x1BD11BDB
    unsigned ksv[3] = {ks0, ks1, ks2};
    const int rotA[4] = {13, 15, 26, 6};
    const int rotB[4] = {17, 29, 16, 24};

    unsigned x0 = c0 + ks0;
    unsigned x1 = c1 + ks1;

#pragma unroll
    for (int i = 0; i < 5; i++) {
#pragma unroll
        for (int j = 0; j < 4; j++) {
            int r = ((i & 1) == 0) ? rotA[j] : rotB[j];
            x0 += x1;
            x1 = rotl32(x1, r);
            x1 ^= x0;
        }
        x0 += ksv[(i + 1) % 3];
        x1 += ksv[(i + 2) % 3] + (unsigned)(i + 1);
    }
    return first ? x0 : x1;
}

// JAX uniform(key, minval=tiny, maxval=1) then gumbel = -log(-log(u)).
// Use double log so --use_fast_math can't perturb argmax.
__device__ __forceinline__ float gumbel_at(unsigned idx) {
    unsigned bits = threefry_out(idx);
    float f = __uint_as_float((bits >> 9) | 0x3f800000u) - 1.0f;
    // floats*(1-tiny)+tiny with (1-tiny)==1 in fp32; then max(tiny, .)
    float u = fmaxf(TINY_F, f + TINY_F);
    double lg = -log(-log((double)u));
    return (float)lg;
}

// ---------------------------------------------------------------------------
// Kernel 1: one block per batch. Channel max + full gate pipeline.
// ---------------------------------------------------------------------------
struct SmemK1 {
    float4 red[256];      // reduction scratch
    float  m[64];         // channel max, 8x8
    float  pre[16];       // pooled 4x4 (pre conv)
    float  c1[16];        // after 1->1 conv
    float  up[64];        // bilinear upsample 8x8
    float  hid[4][64];    // conv5 hidden (relu), 4ch x 8x8
    float  w1[9];
    float  w5[72];        // [4][2][3][3]
    float  b5[4];
    float  w6[36];        // [4][3][3] (oc=1)
    float  b6;
};

__global__ __launch_bounds__(256) void gate_kernel(
    const float* __restrict__ x,
    const float* __restrict__ w1_1,
    const float* __restrict__ w5,
    const float* __restrict__ b5,
    const float* __restrict__ w6,
    const float* __restrict__ b6)
{
    __shared__ SmemK1 s;
    const int t = threadIdx.x;
    const int b = blockIdx.x;

    // load weights
    if (t < 9)  s.w1[t] = w1_1[t];
    if (t < 72) s.w5[t] = w5[t];
    if (t < 4)  s.b5[t] = b5[t];
    if (t < 36) s.w6[t] = w6[t];
    if (t == 0) s.b6 = b6[0];

    // ---- Phase A: channel max (vectorized float4) ----
    // t = grp*16 + v : v = float4 column (16 per row), grp handles 64 channels
    const int v = t & 15;
    const int grp = t >> 4;
    const float4* __restrict__ x4 =
        (const float4*)(x + (size_t)b * CHAN * HW) + (size_t)grp * 64 * 16 + v;

    float4 acc = make_float4(-3.4e38f, -3.4e38f, -3.4e38f, -3.4e38f);
#pragma unroll 4
    for (int i = 0; i < 64; i++) {
        float4 val = x4[i * 16];
        acc.x = fmaxf(acc.x, val.x);
        acc.y = fmaxf(acc.y, val.y);
        acc.z = fmaxf(acc.z, val.z);
        acc.w = fmaxf(acc.w, val.w);
    }
    s.red[t] = acc;
    __syncthreads();

    if (t < 16) {
        float4 m4 = s.red[t];
#pragma unroll
        for (int g = 1; g < 16; g++) {
            float4 o = s.red[g * 16 + t];
            m4.x = fmaxf(m4.x, o.x);
            m4.y = fmaxf(m4.y, o.y);
            m4.z = fmaxf(m4.z, o.z);
            m4.w = fmaxf(m4.w, o.w);
        }
        ((float4*)s.m)[t] = m4;
    }
    __syncthreads();

    // ---- Phase B: windows + probabilistic pooling (t < 16) ----
    if (t < 16) {
        int wh = t >> 2, ww = t & 3;
        float w0 = s.m[(2 * wh) * 8 + 2 * ww];
        float w1v = s.m[(2 * wh) * 8 + 2 * ww + 1];
        float w2 = s.m[(2 * wh + 1) * 8 + 2 * ww];
        float w3 = s.m[(2 * wh + 1) * 8 + 2 * ww + 1];
        float wraw[4] = {w0, w1v, w2, w3};
        float wc[4];
#pragma unroll
        for (int k = 0; k < 4; k++) {
            float val = wraw[k];
            wc[k] = (!isfinite(val) || val < 0.0f) ? EPS_F : val;
        }
        unsigned base = (unsigned)b * 64u + (unsigned)t * 4u;
        int best = 0;
        float bestv = wc[0] + gumbel_at(base);
#pragma unroll
        for (int k = 1; k < 4; k++) {
            float cand = wc[k] + gumbel_at(base + k);
            if (cand > bestv) { bestv = cand; best = k; }
        }
        float mo2 = wc[best];
        float mo3 = fmaxf(fmaxf(w0, w1v), fmaxf(w2, w3));
        float ao4 = (w0 + w1v + w2 + w3) * 0.25f;
        s.pre[t] = 0.1f * mo2 + 0.6f * mo3 + 0.3f * ao4;
    }
    __syncthreads();

    // ---- Phase C: 3x3 SAME conv on 4x4 (bias-free) ----
    if (t < 16) {
        int i = t >> 2, j = t & 3;
        float acc1 = 0.0f;
#pragma unroll
        for (int di = 0; di < 3; di++) {
            int ii = i + di - 1;
            if (ii < 0 || ii >= 4) continue;
#pragma unroll
            for (int dj = 0; dj < 3; dj++) {
                int jj = j + dj - 1;
                if (jj < 0 || jj >= 4) continue;
                acc1 += s.pre[ii * 4 + jj] * s.w1[di * 3 + dj];
            }
        }
        s.c1[t] = acc1;
    }
    __syncthreads();

    // ---- Phase D: bilinear 4->8, jax.image.resize half-pixel weights ----
    if (t < 64) {
        const int j0t[8] = {0, 0, 0, 1, 1, 2, 2, 3};
        const int j1t[8] = {0, 1, 1, 2, 2, 3, 3, 3};
        const float wt[8] = {1.0f, 0.75f, 0.25f, 0.75f, 0.25f, 0.75f, 0.25f, 1.0f};
        int y = t >> 3, xo = t & 7;
        int jy0 = j0t[y], jy1 = j1t[y];
        int jx0 = j0t[xo], jx1 = j1t[xo];
        float wy = wt[y], wx = wt[xo];
        float r0 = wx * s.c1[jy0 * 4 + jx0] + (1.0f - wx) * s.c1[jy0 * 4 + jx1];
        float r1 = wx * s.c1[jy1 * 4 + jx0] + (1.0f - wx) * s.c1[jy1 * 4 + jx1];
        s.up[t] = wy * r0 + (1.0f - wy) * r1;
    }
    __syncthreads();

    // ---- Phase E: conv5 (2ch -> 4ch) + ReLU ----
    if (t < 64) {
        int y = t >> 3, xo = t & 7;
#pragma unroll
        for (int oc = 0; oc < 4; oc++) {
            float acc5 = s.b5[oc];
#pragma unroll
            for (int di = 0; di < 3; di++) {
                int yy = y + di - 1;
                if (yy < 0 || yy >= 8) continue;
#pragma unroll
                for (int dj = 0; dj < 3; dj++) {
                    int xx = xo + dj - 1;
                    if (xx < 0 || xx >= 8) continue;
                    int pix = yy * 8 + xx;
                    acc5 += s.m[pix]  * s.w5[oc * 18 + 0 * 9 + di * 3 + dj];
                    acc5 += s.up[pix] * s.w5[oc * 18 + 1 * 9 + di * 3 + dj];
                }
            }
            s.hid[oc][t] = fmaxf(acc5, 0.0f);
        }
    }
    __syncthreads();

    // ---- Phase F: conv6 (4ch -> 1) + sigmoid -> gate ----
    if (t < 64) {
        int y = t >> 3, xo = t & 7;
        float acc6 = s.b6;
#pragma unroll
        for (int oc = 0; oc < 4; oc++) {
#pragma unroll
            for (int di = 0; di < 3; di++) {
                int yy = y + di - 1;
                if (yy < 0 || yy >= 8) continue;
#pragma unroll
                for (int dj = 0; dj < 3; dj++) {
                    int xx = xo + dj - 1;
                    if (xx < 0 || xx >= 8) continue;
                    acc6 += s.hid[oc][yy * 8 + xx] * s.w6[oc * 9 + di * 3 + dj];
                }
            }
        }
        float gte = 1.0f / (1.0f + expf(-acc6));
        g_gate[b * HW + t] = gte;
    }
}

// ---------------------------------------------------------------------------
// Kernel 2: out = relu(x * gate), fully vectorized float4
// ---------------------------------------------------------------------------
__global__ __launch_bounds__(256) void apply_gate_kernel(
    const float4* __restrict__ x4, float4* __restrict__ out4)
{
    int i = blockIdx.x * blockDim.x + threadIdx.x;
    // n4 = 512*1024*16 = 8388608 == gridDim*blockDim exactly
    // element e = 4*i ; b = e>>16 = i>>14 ; gate4 idx = b*16 + (i & 15)
    int gi = ((i >> 14) << 4) | (i & 15);
    float4 gv = ((const float4*)g_gate)[gi];
    float4 xv = x4[i];
    float4 o;
    o.x = fmaxf(xv.x * gv.x, 0.0f);
    o.y = fmaxf(xv.y * gv.y, 0.0f);
    o.z = fmaxf(xv.z * gv.z, 0.0f);
    o.w = fmaxf(xv.w * gv.w, 0.0f);
    out4[i] = o;
}

extern "C" void kernel_launch(void* const* d_in, const int* in_sizes, int n_in,
                              void* d_out, int out_size)
{
    const float* x    = (const float*)d_in[0];
    const float* w1_1 = (const float*)d_in[1];
    const float* w5   = (const float*)d_in[2];
    const float* b5   = (const float*)d_in[3];
    const float* w6   = (const float*)d_in[4];
    const float* b6   = (const float*)d_in[5];
    float* out = (float*)d_out;

    gate_kernel<<<BATCH, 256>>>(x, w1_1, w5, b5, w6, b6);

    int n4 = BATCH * CHAN * HW / 4; // 8388608
    apply_gate_kernel<<<n4 / 256, 256>>>((const float4*)x, (float4*)out);
}